// round 14
// baseline (speedup 1.0000x reference)
#include <cuda_runtime.h>

#define N_ATOMS 100000
#define N_PAIRS 3200000
#define NT4     (N_PAIRS / 4)    // 800000 thread-work-items
#define ZMAX    96
#define NBLK    148
#define NTHR    1024
#define STRIDE  (NBLK * NTHR)    // 151552
#define STAGES  3

// smem layout (bytes)
#define ZPOW_OFF N_ATOMS                       // 100000
#define RING_OFF (N_ATOMS + ZMAX * 4)          // 100384, 16B aligned
#define STAGE_BYTES (2 * NTHR * 16)            // d | jj : 32KB per stage
#define SMEM_BYTES (RING_OFF + STAGES * STAGE_BYTES)  // 198688

// Scratch (no allocation allowed)
__device__ __align__(16) unsigned char g_z8[N_ATOMS];  // Z in [1,95), 100KB
__device__ float  g_zpow[ZMAX];                        // z^|a_exponent| LUT
__device__ float4 g_params4[3];                        // [0]=c  [1]=e  [2]={inv_a,K,-,-}

__device__ __forceinline__ void cp_async16(unsigned dst_smem, const void* src) {
    asm volatile("cp.async.cg.shared.global [%0], [%1], 16;"
                 :: "r"(dst_smem), "l"(src) : "memory");
}
__device__ __forceinline__ void cp_commit() {
    asm volatile("cp.async.commit_group;" ::: "memory");
}
__device__ __forceinline__ void cp_wait2() {
    asm volatile("cp.async.wait_group 2;" ::: "memory");
}

__global__ void __launch_bounds__(256) prep_kernel(
    const int* __restrict__ Z,
    const float* __restrict__ a_coef, const float* __restrict__ a_exp,
    const float* __restrict__ phi_c,  const float* __restrict__ phi_e,
    const float* __restrict__ ke,     const float* __restrict__ d2A,
    const float* __restrict__ e2m,
    float* __restrict__ out)
{
    int n = blockIdx.x * blockDim.x + threadIdx.x;
    if (n == 0) {
        float a0 = fabsf(phi_c[0]), a1 = fabsf(phi_c[1]),
              a2 = fabsf(phi_c[2]), a3 = fabsf(phi_c[3]);
        float inv_s = 1.0f / (a0 + a1 + a2 + a3);
        g_params4[0] = make_float4(a0 * inv_s, a1 * inv_s, a2 * inv_s, a3 * inv_s);
        g_params4[1] = make_float4(fabsf(phi_e[0]), fabsf(phi_e[1]),
                                   fabsf(phi_e[2]), fabsf(phi_e[3]));
        g_params4[2] = make_float4(1.0f / fabsf(a_coef[0]),
                                   ke[0] * e2m[0] / d2A[0], 0.0f, 0.0f);
    }
    if (n < ZMAX) {
        g_zpow[n] = __powf((float)n, fabsf(a_exp[0]));
    }
    if (n < N_ATOMS) {
        g_z8[n] = (unsigned char)Z[n];
        out[n] = 0.0f;                     // d_out poisoned -> zero it
    }
}

__global__ void __launch_bounds__(NTHR, 1) pair_kernel(
    const float* __restrict__ dist, const float* __restrict__ cut,
    const int*  __restrict__ idx_i, const int*  __restrict__ idx_j,
    float* __restrict__ out)
{
    extern __shared__ unsigned char smem[];
    unsigned char* s_z8   = smem;
    float*         s_zpow = (float*)(smem + ZPOW_OFF);
    float4*        ring   = (float4*)(smem + RING_OFF);

    int tid = threadIdx.x;

    // Stage 100KB Z table + LUT into smem (L2-resident source)
    {
        const int4* src = (const int4*)g_z8;
        int4*       dst = (int4*)s_z8;
        #pragma unroll 4
        for (int i = tid; i < N_ATOMS / 16; i += NTHR) dst[i] = src[i];
        if (tid < ZMAX) s_zpow[tid] = g_zpow[tid];
    }
    __syncthreads();

    float4 C  = g_params4[0];
    float4 E  = g_params4[1];
    float4 P2 = g_params4[2];
    float inv_a = P2.x, K = P2.y;

    // Per-thread private ring slots (no cross-thread sharing -> no barriers)
    const unsigned ring_base = (unsigned)__cvta_generic_to_shared(ring);
    // slot(stage, arr): arr 0 = d, arr 1 = jj
    #define SLOT(stage, arr) (ring_base + (((stage) * 2 + (arr)) * NTHR + tid) * 16u)

    const int t0 = blockIdx.x * NTHR + tid;

    // Prologue: issue STAGES stages, one commit group each
    #pragma unroll
    for (int s = 0; s < STAGES; s++) {
        int ts = t0 + s * STRIDE;
        if (ts < NT4) {
            cp_async16(SLOT(s, 0), dist  + 4 * ts);
            cp_async16(SLOT(s, 1), idx_j + 4 * ts);
        }
        cp_commit();
    }
    // Register prefetch for iteration 0 (ct, si)
    float4 ct_cur = __ldg((const float4*)cut + t0);
    int4   si_cur = __ldg((const int4*)idx_i + t0);

    int t = t0;
    int k = 0;
    while (t < NT4) {
        int tn = t + STRIDE;
        bool vn = tn < NT4;

        // Register prefetch for next iteration (lands during this compute)
        float4 ct_next;
        int4   si_next;
        if (vn) {
            ct_next = __ldg((const float4*)cut + tn);
            si_next = __ldg((const int4*)idx_i + tn);
        }

        cp_wait2();                          // stage k complete (issued 3 iters ago)
        int slot = k % STAGES;
        float4 d  = ring[(slot * 2 + 0) * NTHR + tid];
        int4   sj = *(const int4*)&ring[(slot * 2 + 1) * NTHR + tid];
        int4   si = si_cur;
        float4 ct = ct_cur;

        // Refill freed slot for stage k+STAGES (after the LDS reads above)
        int tf = t + STAGES * STRIDE;
        if (tf < NT4) {
            cp_async16(SLOT(slot, 0), dist  + 4 * tf);
            cp_async16(SLOT(slot, 1), idx_j + 4 * tf);
        }
        cp_commit();

        int zi0 = s_z8[si.x], zi1 = s_z8[si.y], zi2 = s_z8[si.z], zi3 = s_z8[si.w];
        int zj0 = s_z8[sj.x], zj1 = s_z8[sj.y], zj2 = s_z8[sj.z], zj3 = s_z8[sj.w];

        float a0 = d.x * (s_zpow[zi0] + s_zpow[zj0]) * inv_a;
        float a1 = d.y * (s_zpow[zi1] + s_zpow[zj1]) * inv_a;
        float a2 = d.z * (s_zpow[zi2] + s_zpow[zj2]) * inv_a;
        float a3 = d.w * (s_zpow[zi3] + s_zpow[zj3]) * inv_a;

        float p0 = C.x * __expf(-E.x * a0) + C.y * __expf(-E.y * a0)
                 + C.z * __expf(-E.z * a0) + C.w * __expf(-E.w * a0);
        float p1 = C.x * __expf(-E.x * a1) + C.y * __expf(-E.y * a1)
                 + C.z * __expf(-E.z * a1) + C.w * __expf(-E.w * a1);
        float p2 = C.x * __expf(-E.x * a2) + C.y * __expf(-E.y * a2)
                 + C.z * __expf(-E.z * a2) + C.w * __expf(-E.w * a2);
        float p3 = C.x * __expf(-E.x * a3) + C.y * __expf(-E.y * a3)
                 + C.z * __expf(-E.z * a3) + C.w * __expf(-E.w * a3);

        float v0 = K * (float)(zi0 * zj0) * p0 * ct.x * __fdividef(1.0f, d.x);
        float v1 = K * (float)(zi1 * zj1) * p1 * ct.y * __fdividef(1.0f, d.y);
        float v2 = K * (float)(zi2 * zj2) * p2 * ct.z * __fdividef(1.0f, d.z);
        float v3 = K * (float)(zi3 * zj3) * p3 * ct.w * __fdividef(1.0f, d.w);

        // Thread-local segmented accumulation; fire-and-forget atomics at
        // boundaries (idx_i sorted, ~32 pairs/segment).
        int   seg = si.x;
        float acc = v0;
        #define ZSTEP(S, V) \
            if ((S) == seg) acc += (V); \
            else { atomicAdd(&out[seg], acc); seg = (S); acc = (V); }
        ZSTEP(si.y, v1) ZSTEP(si.z, v2) ZSTEP(si.w, v3)
        #undef ZSTEP
        atomicAdd(&out[seg], acc);

        ct_cur = ct_next;
        si_cur = si_next;
        t = tn;
        k++;
    }
    #undef SLOT
}

extern "C" void kernel_launch(void* const* d_in, const int* in_sizes, int n_in,
                              void* d_out, int out_size)
{
    const int*   Z    = (const int*)  d_in[0];
    const float* dist = (const float*)d_in[1];
    const float* cutv = (const float*)d_in[2];
    const int*   ii   = (const int*)  d_in[3];
    const int*   jj   = (const int*)  d_in[4];
    const float* ac   = (const float*)d_in[5];
    const float* ae   = (const float*)d_in[6];
    const float* pc   = (const float*)d_in[7];
    const float* pe   = (const float*)d_in[8];
    const float* ke   = (const float*)d_in[9];
    const float* d2A  = (const float*)d_in[10];
    const float* e2m  = (const float*)d_in[11];
    float* out = (float*)d_out;

    cudaFuncSetAttribute(pair_kernel,
                         cudaFuncAttributeMaxDynamicSharedMemorySize, SMEM_BYTES);

    prep_kernel<<<(N_ATOMS + 255) / 256, 256>>>(Z, ac, ae, pc, pe, ke, d2A, e2m, out);
    pair_kernel<<<NBLK, NTHR, SMEM_BYTES>>>(dist, cutv, ii, jj, out);
}

// round 15
// speedup vs baseline: 1.1151x; 1.1151x over previous
#include <cuda_runtime.h>

#define N_ATOMS 100000
#define N_PAIRS 3200000
#define NT4     (N_PAIRS / 4)    // 800000 thread-work-items
#define ZMAX    96
#define NBLK    148
#define NTHR    960
#define STRIDE  (NBLK * NTHR)    // 142080
#define STAGES  2

// smem layout (bytes)
#define ZPOW_OFF N_ATOMS                       // 100000
#define RING_OFF (N_ATOMS + ZMAX * 4)          // 100384, 16B aligned
#define STAGE_F4 (4 * NTHR)                    // float4 slots/stage: d|ct|jj|ii
#define SMEM_BYTES (RING_OFF + STAGES * STAGE_F4 * 16)   // 223264

// Scratch (no allocation allowed)
__device__ __align__(16) unsigned char g_z8[N_ATOMS];  // Z in [1,95), 100KB
__device__ float  g_zpow[ZMAX];                        // z^|a_exponent| LUT
__device__ float4 g_params4[3];                        // [0]=c  [1]=e  [2]={inv_a,K,-,-}

__device__ __forceinline__ void cp_async16(unsigned dst_smem, const void* src) {
    asm volatile("cp.async.cg.shared.global [%0], [%1], 16;"
                 :: "r"(dst_smem), "l"(src) : "memory");
}
__device__ __forceinline__ void cp_commit() {
    asm volatile("cp.async.commit_group;" ::: "memory");
}
__device__ __forceinline__ void cp_wait1() {
    asm volatile("cp.async.wait_group 1;" ::: "memory");
}

__global__ void __launch_bounds__(256) prep_kernel(
    const int* __restrict__ Z,
    const float* __restrict__ a_coef, const float* __restrict__ a_exp,
    const float* __restrict__ phi_c,  const float* __restrict__ phi_e,
    const float* __restrict__ ke,     const float* __restrict__ d2A,
    const float* __restrict__ e2m,
    float* __restrict__ out)
{
    int n = blockIdx.x * blockDim.x + threadIdx.x;
    if (n == 0) {
        float a0 = fabsf(phi_c[0]), a1 = fabsf(phi_c[1]),
              a2 = fabsf(phi_c[2]), a3 = fabsf(phi_c[3]);
        float inv_s = 1.0f / (a0 + a1 + a2 + a3);
        g_params4[0] = make_float4(a0 * inv_s, a1 * inv_s, a2 * inv_s, a3 * inv_s);
        g_params4[1] = make_float4(fabsf(phi_e[0]), fabsf(phi_e[1]),
                                   fabsf(phi_e[2]), fabsf(phi_e[3]));
        g_params4[2] = make_float4(1.0f / fabsf(a_coef[0]),
                                   ke[0] * e2m[0] / d2A[0], 0.0f, 0.0f);
    }
    if (n < ZMAX) {
        g_zpow[n] = __powf((float)n, fabsf(a_exp[0]));
    }
    if (n < N_ATOMS) {
        g_z8[n] = (unsigned char)Z[n];
        out[n] = 0.0f;                     // d_out poisoned -> zero it
    }
}

__global__ void __launch_bounds__(NTHR, 1) pair_kernel(
    const float* __restrict__ dist, const float* __restrict__ cut,
    const int*  __restrict__ idx_i, const int*  __restrict__ idx_j,
    float* __restrict__ out)
{
    extern __shared__ unsigned char smem[];
    unsigned char* s_z8   = smem;
    float*         s_zpow = (float*)(smem + ZPOW_OFF);
    float4*        ring   = (float4*)(smem + RING_OFF);

    int tid = threadIdx.x;

    // Stage 100KB Z table + LUT into smem (L2-resident source)
    {
        const int4* src = (const int4*)g_z8;
        int4*       dst = (int4*)s_z8;
        #pragma unroll 4
        for (int i = tid; i < N_ATOMS / 16; i += NTHR) dst[i] = src[i];
        if (tid < ZMAX) s_zpow[tid] = g_zpow[tid];
    }
    __syncthreads();

    float4 C  = g_params4[0];
    float4 E  = g_params4[1];
    float4 P2 = g_params4[2];
    float inv_a = P2.x, K = P2.y;

    // Per-thread private ring slots (per-thread cp.async groups -> no barriers)
    const unsigned ring_base = (unsigned)__cvta_generic_to_shared(ring);
    const unsigned slot_d  = ring_base + (0 * NTHR + tid) * 16;
    const unsigned slot_ct = ring_base + (1 * NTHR + tid) * 16;
    const unsigned slot_jj = ring_base + (2 * NTHR + tid) * 16;
    const unsigned slot_ii = ring_base + (3 * NTHR + tid) * 16;
    const unsigned stage_bytes = STAGE_F4 * 16;

    int t = blockIdx.x * NTHR + tid;       // always < NT4 initially

    // Prologue: stage 0 in flight
    cp_async16(slot_d,  dist  + 4 * t);
    cp_async16(slot_ct, cut   + 4 * t);
    cp_async16(slot_jj, idx_j + 4 * t);
    cp_async16(slot_ii, idx_i + 4 * t);
    cp_commit();

    int k = 0;
    bool valid = true;
    while (valid) {
        int tn = t + STRIDE;
        bool vn = tn < NT4;

        // Issue next stage before waiting (keeps DRAM busy through compute)
        unsigned off_n = ((k + 1) & 1) * stage_bytes;
        if (vn) {
            cp_async16(slot_d  + off_n, dist  + 4 * tn);
            cp_async16(slot_ct + off_n, cut   + 4 * tn);
            cp_async16(slot_jj + off_n, idx_j + 4 * tn);
            cp_async16(slot_ii + off_n, idx_i + 4 * tn);
        }
        cp_commit();
        cp_wait1();                         // current stage's data is ready

        int base = ((k & 1) ? STAGE_F4 : 0) + tid;
        float4 d  = ring[base];
        float4 ct = ring[base + NTHR];
        int4   sj = *(const int4*)&ring[base + 2 * NTHR];
        int4   si = *(const int4*)&ring[base + 3 * NTHR];

        int zi0 = s_z8[si.x], zi1 = s_z8[si.y], zi2 = s_z8[si.z], zi3 = s_z8[si.w];
        int zj0 = s_z8[sj.x], zj1 = s_z8[sj.y], zj2 = s_z8[sj.z], zj3 = s_z8[sj.w];

        float a0 = d.x * (s_zpow[zi0] + s_zpow[zj0]) * inv_a;
        float a1 = d.y * (s_zpow[zi1] + s_zpow[zj1]) * inv_a;
        float a2 = d.z * (s_zpow[zi2] + s_zpow[zj2]) * inv_a;
        float a3 = d.w * (s_zpow[zi3] + s_zpow[zj3]) * inv_a;

        float p0 = C.x * __expf(-E.x * a0) + C.y * __expf(-E.y * a0)
                 + C.z * __expf(-E.z * a0) + C.w * __expf(-E.w * a0);
        float p1 = C.x * __expf(-E.x * a1) + C.y * __expf(-E.y * a1)
                 + C.z * __expf(-E.z * a1) + C.w * __expf(-E.w * a1);
        float p2 = C.x * __expf(-E.x * a2) + C.y * __expf(-E.y * a2)
                 + C.z * __expf(-E.z * a2) + C.w * __expf(-E.w * a2);
        float p3 = C.x * __expf(-E.x * a3) + C.y * __expf(-E.y * a3)
                 + C.z * __expf(-E.z * a3) + C.w * __expf(-E.w * a3);

        float v0 = K * (float)(zi0 * zj0) * p0 * ct.x * __fdividef(1.0f, d.x);
        float v1 = K * (float)(zi1 * zj1) * p1 * ct.y * __fdividef(1.0f, d.y);
        float v2 = K * (float)(zi2 * zj2) * p2 * ct.z * __fdividef(1.0f, d.z);
        float v3 = K * (float)(zi3 * zj3) * p3 * ct.w * __fdividef(1.0f, d.w);

        // Thread-local segmented accumulation; fire-and-forget atomics at
        // boundaries (idx_i sorted, ~32 pairs/segment).
        int   seg = si.x;
        float acc = v0;
        #define ZSTEP(S, V) \
            if ((S) == seg) acc += (V); \
            else { atomicAdd(&out[seg], acc); seg = (S); acc = (V); }
        ZSTEP(si.y, v1) ZSTEP(si.z, v2) ZSTEP(si.w, v3)
        #undef ZSTEP
        atomicAdd(&out[seg], acc);

        t = tn;
        valid = vn;
        k++;
    }
}

extern "C" void kernel_launch(void* const* d_in, const int* in_sizes, int n_in,
                              void* d_out, int out_size)
{
    const int*   Z    = (const int*)  d_in[0];
    const float* dist = (const float*)d_in[1];
    const float* cutv = (const float*)d_in[2];
    const int*   ii   = (const int*)  d_in[3];
    const int*   jj   = (const int*)  d_in[4];
    const float* ac   = (const float*)d_in[5];
    const float* ae   = (const float*)d_in[6];
    const float* pc   = (const float*)d_in[7];
    const float* pe   = (const float*)d_in[8];
    const float* ke   = (const float*)d_in[9];
    const float* d2A  = (const float*)d_in[10];
    const float* e2m  = (const float*)d_in[11];
    float* out = (float*)d_out;

    cudaFuncSetAttribute(pair_kernel,
                         cudaFuncAttributeMaxDynamicSharedMemorySize, SMEM_BYTES);

    prep_kernel<<<(N_ATOMS + 255) / 256, 256>>>(Z, ac, ae, pc, pe, ke, d2A, e2m, out);
    pair_kernel<<<NBLK, NTHR, SMEM_BYTES>>>(dist, cutv, ii, jj, out);
}